// round 2
// baseline (speedup 1.0000x reference)
#include <cuda_runtime.h>
#include <cstdint>

#define BB 256
#define CC 2048
#define HWN 49
#define KK 16
typedef unsigned long long ull;

// Device scratch (static allocation — no runtime allocs allowed)
__device__ float g_part[BB * 8 * 784];   // per-(b, c-slice) partial conv sums [b][q][k*49+hw]
__device__ float g_fc16[BB * 784];       // BN'd, /49 featcov16, layout [b][hw*16+k]
__device__ float g_wT[CC * KK];          // transposed conv weight [c][16]
__device__ float g_binv[KK], g_boff[KK];

// ---- f32x2 helpers ----
__device__ __forceinline__ ull ffma2(ull a, ull b, ull c) {
    ull d;
    asm("fma.rn.f32x2 %0, %1, %2, %3;" : "=l"(d) : "l"(a), "l"(b), "l"(c));
    return d;
}
__device__ __forceinline__ ull pack2(float x, float y) {
    ull r;
    asm("mov.b64 %0, {%1, %2};" : "=l"(r) : "f"(x), "f"(y));
    return r;
}
__device__ __forceinline__ void unpack2(ull v, float& x, float& y) {
    asm("mov.b64 {%0, %1}, %2;" : "=f"(x), "=f"(y) : "l"(v));
}

// ============================================================================
// K0: transpose w16 -> wT[c][16]; precompute BN scale/offset (with 1/49 folded)
// ============================================================================
__global__ void k0_prep(const float* __restrict__ w16,
                        const float* __restrict__ bng, const float* __restrict__ bnb,
                        const float* __restrict__ bnm, const float* __restrict__ bnv) {
    int idx = blockIdx.x * 256 + threadIdx.x;
    if (idx < CC * KK) {
        int c = idx >> 4, k = idx & 15;
        g_wT[idx] = w16[k * CC + c];
    }
    if (blockIdx.x == 0 && threadIdx.x < KK) {
        int k = threadIdx.x;
        float iv = bng[k] * rsqrtf(bnv[k] + 1e-5f);
        g_binv[k] = iv * (1.0f / 49.0f);
        g_boff[k] = (bnb[k] - bnm[k] * iv) * (1.0f / 49.0f);
    }
}

// ============================================================================
// K1: partial conv. Block = (c-slice q of 256 channels, batch b).
// Warp w owns 32 channels; lanes = hw (lane and lane+32). Weights via
// uniform LDG.128 from g_wT (L1-resident). No syncthreads in main loop.
// ============================================================================
__global__ __launch_bounds__(256) void k1_conv(const float* __restrict__ fm) {
    __shared__ float red[8 * 784];
    const int b = blockIdx.y, q = blockIdx.x;
    const int tid = threadIdx.x;
    const int lane = tid & 31, wid = tid >> 5;

    const float* fmc = fm + (size_t)b * (CC * HWN) + (size_t)(q * 256 + wid * 32) * HWN;
    const float* wq = g_wT + (q * 256 + wid * 32) * KK;

    ull acc0[8], acc1[8];
#pragma unroll
    for (int i = 0; i < 8; i++) { acc0[i] = 0ull; acc1[i] = 0ull; }

#pragma unroll 4
    for (int j = 0; j < 32; j++) {
        float v0 = fmc[j * HWN + lane];
        float v1 = (lane < 17) ? fmc[j * HWN + lane + 32] : 0.0f;
        ull vv0 = pack2(v0, v0);
        ull vv1 = pack2(v1, v1);
        const ulonglong2* wp = (const ulonglong2*)(wq + j * KK);
        ulonglong2 wA = wp[0], wB = wp[1], wC = wp[2], wD = wp[3];
        acc0[0] = ffma2(wA.x, vv0, acc0[0]);  acc1[0] = ffma2(wA.x, vv1, acc1[0]);
        acc0[1] = ffma2(wA.y, vv0, acc0[1]);  acc1[1] = ffma2(wA.y, vv1, acc1[1]);
        acc0[2] = ffma2(wB.x, vv0, acc0[2]);  acc1[2] = ffma2(wB.x, vv1, acc1[2]);
        acc0[3] = ffma2(wB.y, vv0, acc0[3]);  acc1[3] = ffma2(wB.y, vv1, acc1[3]);
        acc0[4] = ffma2(wC.x, vv0, acc0[4]);  acc1[4] = ffma2(wC.x, vv1, acc1[4]);
        acc0[5] = ffma2(wC.y, vv0, acc0[5]);  acc1[5] = ffma2(wC.y, vv1, acc1[5]);
        acc0[6] = ffma2(wD.x, vv0, acc0[6]);  acc1[6] = ffma2(wD.x, vv1, acc1[6]);
        acc0[7] = ffma2(wD.y, vv0, acc0[7]);  acc1[7] = ffma2(wD.y, vv1, acc1[7]);
    }

    // per-warp partials -> smem
#pragma unroll
    for (int kp = 0; kp < 8; kp++) {
        float a, c0;
        unpack2(acc0[kp], a, c0);
        red[wid * 784 + (2 * kp) * 49 + lane] = a;
        red[wid * 784 + (2 * kp + 1) * 49 + lane] = c0;
        if (lane < 17) {
            float x, y;
            unpack2(acc1[kp], x, y);
            red[wid * 784 + (2 * kp) * 49 + lane + 32] = x;
            red[wid * 784 + (2 * kp + 1) * 49 + lane + 32] = y;
        }
    }
    __syncthreads();

    float* dst = g_part + ((size_t)b * 8 + q) * 784;
    for (int o = tid; o < 784; o += 256) {
        float s = 0.0f;
#pragma unroll
        for (int w = 0; w < 8; w++) s += red[w * 784 + o];
        dst[o] = s;
    }
}

// ============================================================================
// K1b: reduce 8 c-slices, apply BN (+1/49), relayout to [hw][16]
// ============================================================================
__global__ __launch_bounds__(256) void k1b_reduce() {
    const int b = blockIdx.x;
    const float* src = g_part + (size_t)b * 8 * 784;
    for (int o = threadIdx.x; o < 784; o += 256) {
        float s = 0.0f;
#pragma unroll
        for (int qq = 0; qq < 8; qq++) s += src[qq * 784 + o];
        int k = o / 49;
        int hw = o - k * 49;
        g_fc16[b * 784 + hw * 16 + k] = s * g_binv[k] + g_boff[k];
    }
}

// ============================================================================
// K2: bilinear pooling. out[b, k*2048+c] = sum_hw fc16[b,hw,k] * fm[b,c,hw]
// Block = (c-tile of 224, b). Thread = one c. featmap tile staged via float4;
// fc16 read as 16B quads (LDS.128 broadcast): 5 LDS wavefronts / 8 FFMA2 per hw.
// ============================================================================
__global__ __launch_bounds__(224) void k2_bilinear(const float* __restrict__ fm,
                                                   float* __restrict__ out) {
    __shared__ float fms[224 * 49];                 // 43904 B
    __shared__ __align__(16) float fcs[784];        // [hw][16], 3136 B

    const int tid = threadIdx.x;
    const int b = blockIdx.y;
    const int ct = blockIdx.x;
    const int cbase = ct * 224;
    const int ccount = min(224, CC - cbase);

    // stage fc16 (already [hw][16] layout)
    for (int idx = tid; idx < 784; idx += 224) fcs[idx] = g_fc16[b * 784 + idx];
    // stage featmap tile (contiguous, exact float4 multiple)
    const float* fmb = fm + (size_t)b * (CC * HWN) + (size_t)cbase * HWN;
    const int n4 = (ccount * HWN) >> 2;
    for (int i = tid; i < n4; i += 224)
        ((float4*)fms)[i] = ((const float4*)fmb)[i];
    __syncthreads();

    if (tid < ccount) {
        ull acc[8];
#pragma unroll
        for (int i = 0; i < 8; i++) acc[i] = 0ull;
        const float* row = &fms[tid * HWN];
#pragma unroll 7
        for (int hw = 0; hw < HWN; hw++) {
            float v = row[hw];
            ull vv = pack2(v, v);
            const ulonglong2* fq = (const ulonglong2*)(fcs + hw * 16);
            ulonglong2 q0 = fq[0], q1 = fq[1], q2 = fq[2], q3 = fq[3];
            acc[0] = ffma2(q0.x, vv, acc[0]);
            acc[1] = ffma2(q0.y, vv, acc[1]);
            acc[2] = ffma2(q1.x, vv, acc[2]);
            acc[3] = ffma2(q1.y, vv, acc[3]);
            acc[4] = ffma2(q2.x, vv, acc[4]);
            acc[5] = ffma2(q2.y, vv, acc[5]);
            acc[6] = ffma2(q3.x, vv, acc[6]);
            acc[7] = ffma2(q3.y, vv, acc[7]);
        }
        float* ob = out + (size_t)b * 32768 + cbase + tid;
#pragma unroll
        for (int kp = 0; kp < 8; kp++) {
            float x, y;
            unpack2(acc[kp], x, y);
            ob[(2 * kp) * 2048] = x;
            ob[(2 * kp + 1) * 2048] = y;
        }
    }
}

extern "C" void kernel_launch(void* const* d_in, const int* in_sizes, int n_in,
                              void* d_out, int out_size) {
    const float* fm  = (const float*)d_in[0];  // [256,2048,7,7]
    const float* w16 = (const float*)d_in[1];  // [16,2048]
    const float* bng = (const float*)d_in[2];
    const float* bnb = (const float*)d_in[3];
    const float* bnm = (const float*)d_in[4];
    const float* bnv = (const float*)d_in[5];
    float* out = (float*)d_out;                // [256, 32768]

    k0_prep<<<(CC * KK + 255) / 256, 256>>>(w16, bng, bnb, bnm, bnv);
    dim3 g1(8, BB);            // 2048 blocks: (c-slice, b)
    k1_conv<<<g1, 256>>>(fm);
    k1b_reduce<<<BB, 256>>>();
    dim3 g2(10, BB);           // 2560 blocks: (c-tile, b)
    k2_bilinear<<<g2, 224>>>(fm, out);
}